// round 1
// baseline (speedup 1.0000x reference)
#include <cuda_runtime.h>
#include <math.h>

#define BATCH 16384

// ---------------- scratch (static device arrays; no allocations) ----------------
__device__ float g_h400 [BATCH*400];
__device__ float g_out  [BATCH*256];
__device__ float g_tmp  [BATCH*256];
__device__ float g_emb  [BATCH*256];
__device__ float g_si   [BATCH*256];
__device__ float g_logit[BATCH*64];
__device__ float g_gsel [3*BATCH*64];
__device__ float g_fraw [BATCH*8];
__device__ float g_fsel [BATCH*8];
__device__ float g_hbig [(size_t)8*BATCH*256];

// deterministic two-stage batchnorm reductions (no atomics)
#define NPART 64
__device__ float g_psum1[NPART*256],  g_psq1[NPART*256];
__device__ float g_psum2[NPART*2048], g_psq2[NPART*2048];
__device__ float g_mean1[256],  g_istd1[256];
__device__ float g_mean2[2048], g_istd2[2048];

enum { EPI_NONE=0, EPI_RELU=1, EPI_TANH=2, EPI_MULRELU=3, EPI_DUAL=4 };

// ---------------- generic SGEMM: C[M,N] = A[M,K] @ B[K,N] + bias, epilogue ----------------
// BM=128, BN=128, BK=16, 256 threads, 8x8 microtile.
__global__ void __launch_bounds__(256) sgemm(
    const float* __restrict__ A, const float* __restrict__ Bw,
    const float* __restrict__ bias, float* __restrict__ C,
    float* __restrict__ C2, const float* __restrict__ aux,
    int N, int K, int epi)
{
    __shared__ float As[16][128];
    __shared__ float Bs[16][128];
    int tid = threadIdx.x;
    int tx = tid & 15, ty = tid >> 4;
    int rowBase = blockIdx.y * 128;
    int colBase = blockIdx.x * 128;

    float acc[8][8];
    #pragma unroll
    for (int i=0;i<8;i++)
        #pragma unroll
        for (int j=0;j<8;j++) acc[i][j]=0.f;

    int aRow = tid >> 1;          // 0..127
    int aCol = (tid & 1) * 8;     // 0 or 8
    int bRow = tid >> 4;          // 0..15
    int bCol = (tid & 15) * 8;    // 0..120

    for (int kt = 0; kt < K; kt += 16) {
        { // A tile (K always multiple of 16 here; M multiple of 128)
            const float* ap = A + (size_t)(rowBase + aRow) * K + kt + aCol;
            float4 v0 = *(const float4*)(ap);
            float4 v1 = *(const float4*)(ap + 4);
            As[aCol+0][aRow]=v0.x; As[aCol+1][aRow]=v0.y; As[aCol+2][aRow]=v0.z; As[aCol+3][aRow]=v0.w;
            As[aCol+4][aRow]=v1.x; As[aCol+5][aRow]=v1.y; As[aCol+6][aRow]=v1.z; As[aCol+7][aRow]=v1.w;
        }
        { // B tile (mask N edge)
            int gc = colBase + bCol;
            const float* bp = Bw + (size_t)(kt + bRow) * N + gc;
            if (gc + 7 < N) {
                *(float4*)&Bs[bRow][bCol]   = *(const float4*)(bp);
                *(float4*)&Bs[bRow][bCol+4] = *(const float4*)(bp + 4);
            } else {
                #pragma unroll
                for (int e=0;e<8;e++)
                    Bs[bRow][bCol+e] = (gc+e < N) ? bp[e] : 0.f;
            }
        }
        __syncthreads();
        #pragma unroll
        for (int k=0;k<16;k++) {
            float4 a0 = *(const float4*)&As[k][ty*8];
            float4 a1 = *(const float4*)&As[k][ty*8+4];
            float4 b0 = *(const float4*)&Bs[k][tx*8];
            float4 b1 = *(const float4*)&Bs[k][tx*8+4];
            float av[8]={a0.x,a0.y,a0.z,a0.w,a1.x,a1.y,a1.z,a1.w};
            float bv[8]={b0.x,b0.y,b0.z,b0.w,b1.x,b1.y,b1.z,b1.w};
            #pragma unroll
            for (int i=0;i<8;i++)
                #pragma unroll
                for (int j=0;j<8;j++)
                    acc[i][j] += av[i]*bv[j];
        }
        __syncthreads();
    }

    #pragma unroll
    for (int i=0;i<8;i++) {
        int row = rowBase + ty*8 + i;
        #pragma unroll
        for (int j=0;j<8;j++) {
            int col = colBase + tx*8 + j;
            if (col < N) {
                float v = acc[i][j] + bias[col];
                size_t idx = (size_t)row * N + col;
                if      (epi == EPI_NONE)    C[idx] = v;
                else if (epi == EPI_RELU)    C[idx] = fmaxf(v, 0.f);
                else if (epi == EPI_TANH)    C[idx] = tanhf(v);
                else if (epi == EPI_MULRELU) C[idx] = fmaxf(v * aux[idx], 0.f);
                else                         { C[idx] = v; C2[idx] = fmaxf(v, 0.f); }
            }
        }
    }
}

// ---------------- mod einsum GEMM: per m, hbig[m] = (bn1(out)*g1[m]+b1[m]) @ mod_W[m] + mod_b[m] ----------------
__global__ void __launch_bounds__(256) modgemm(
    const float* __restrict__ modW, const float* __restrict__ modb,
    const float* __restrict__ g1, const float* __restrict__ b1)
{
    __shared__ float As[16][128];
    __shared__ float Bs[16][128];
    int tid = threadIdx.x;
    int tx = tid & 15, ty = tid >> 4;
    int rowBase = blockIdx.y * 128;
    int colBase = blockIdx.x * 128;
    int m = blockIdx.z;
    const float* Bw = modW + (size_t)m * 65536;

    float acc[8][8];
    #pragma unroll
    for (int i=0;i<8;i++)
        #pragma unroll
        for (int j=0;j<8;j++) acc[i][j]=0.f;

    int aRow = tid >> 1;
    int aCol = (tid & 1) * 8;
    int bRow = tid >> 4;
    int bCol = (tid & 15) * 8;

    for (int kt = 0; kt < 256; kt += 16) {
        {
            const float* ap = g_out + (size_t)(rowBase + aRow) * 256 + kt + aCol;
            float4 v0 = *(const float4*)(ap);
            float4 v1 = *(const float4*)(ap + 4);
            float vv[8]={v0.x,v0.y,v0.z,v0.w,v1.x,v1.y,v1.z,v1.w};
            #pragma unroll
            for (int c=0;c<8;c++) {
                int k = kt + aCol + c;
                As[aCol+c][aRow] =
                    (vv[c] - g_mean1[k]) * g_istd1[k] * g1[m*256+k] + b1[m*256+k];
            }
        }
        {
            const float* bp = Bw + (size_t)(kt + bRow) * 256 + colBase + bCol;
            *(float4*)&Bs[bRow][bCol]   = *(const float4*)(bp);
            *(float4*)&Bs[bRow][bCol+4] = *(const float4*)(bp + 4);
        }
        __syncthreads();
        #pragma unroll
        for (int k=0;k<16;k++) {
            float4 a0 = *(const float4*)&As[k][ty*8];
            float4 a1 = *(const float4*)&As[k][ty*8+4];
            float4 b0 = *(const float4*)&Bs[k][tx*8];
            float4 b1 = *(const float4*)&Bs[k][tx*8+4];
            float av[8]={a0.x,a0.y,a0.z,a0.w,a1.x,a1.y,a1.z,a1.w};
            float bv[8]={b0.x,b0.y,b0.z,b0.w,b1.x,b1.y,b1.z,b1.w};
            #pragma unroll
            for (int i=0;i<8;i++)
                #pragma unroll
                for (int j=0;j<8;j++)
                    acc[i][j] += av[i]*bv[j];
        }
        __syncthreads();
    }

    #pragma unroll
    for (int i=0;i<8;i++) {
        int row = rowBase + ty*8 + i;
        #pragma unroll
        for (int j=0;j<8;j++) {
            int col = colBase + tx*8 + j;
            g_hbig[((size_t)m*BATCH + row)*256 + col] = acc[i][j] + modb[m*256+col];
        }
    }
}

// ---------------- batchnorm stats (deterministic 2-stage) ----------------
// stage 1: per-(row-block, column) partial sums. grid(slabs, NPART), 256 thr.
__global__ void colstats(const float* __restrict__ X,
                         float* __restrict__ psum, float* __restrict__ psq,
                         int ncols)
{
    int slab = blockIdx.x;
    int col  = threadIdx.x;
    int c    = slab*256 + col;
    const float* base = X + (size_t)slab * BATCH * 256;
    int rpb = BATCH / NPART;
    int r0  = blockIdx.y * rpb;
    float s = 0.f, q = 0.f;
    for (int r = r0; r < r0 + rpb; r++) {
        float v = base[(size_t)r*256 + col];
        s += v; q += v*v;
    }
    psum[(size_t)blockIdx.y*ncols + c] = s;
    psq [(size_t)blockIdx.y*ncols + c] = q;
}

// stage 2: reduce NPART partials, produce mean + rsqrt(var+eps)
__global__ void bnfinal(const float* __restrict__ psum, const float* __restrict__ psq,
                        float* __restrict__ mean, float* __restrict__ istd, int n)
{
    int i = blockIdx.x*blockDim.x + threadIdx.x;
    if (i >= n) return;
    float s = 0.f, q = 0.f;
    for (int p = 0; p < NPART; p++) { s += psum[(size_t)p*n + i]; q += psq[(size_t)p*n + i]; }
    float mu  = s * (1.f/BATCH);
    float var = q * (1.f/BATCH) - mu*mu;
    mean[i] = mu;
    istd[i] = rsqrtf(var + 1e-5f);
}

// ---------------- gumbel softmax ----------------
__device__ __forceinline__ float gnoise(float u) {
    u = fminf(fmaxf(u, 1e-10f), 1.0f - 1e-7f);
    return -logf(-logf(u));
}

// per (sample, m) row of 8
__global__ void gumbel_sel(const float* __restrict__ u, int i)
{
    int t = blockIdx.x*blockDim.x + threadIdx.x;
    if (t >= BATCH*8) return;
    int b = t >> 3, m = t & 7;
    const float* lp = g_logit + b*64 + m*8;
    const float* up = u + (size_t)b*192 + i*64 + m*8;
    float z[8]; float mx = -3.4e38f;
    #pragma unroll
    for (int k=0;k<8;k++){ z[k] = lp[k] + gnoise(up[k]); mx = fmaxf(mx, z[k]); }
    float s = 0.f;
    #pragma unroll
    for (int k=0;k<8;k++){ z[k] = expf(z[k]-mx); s += z[k]; }
    float inv = 1.f/s;
    float* op = g_gsel + (size_t)i*BATCH*64 + b*64 + m*8;
    #pragma unroll
    for (int k=0;k<8;k++) op[k] = z[k]*inv;
}

__global__ void gumbel_fin(const float* __restrict__ u)
{
    int b = blockIdx.x*blockDim.x + threadIdx.x;
    if (b >= BATCH) return;
    float z[8]; float mx = -3.4e38f;
    #pragma unroll
    for (int k=0;k<8;k++){ z[k] = g_fraw[b*8+k] + gnoise(u[b*8+k]); mx = fmaxf(mx, z[k]); }
    float s = 0.f;
    #pragma unroll
    for (int k=0;k<8;k++){ z[k] = expf(z[k]-mx); s += z[k]; }
    float inv = 1.f/s;
    #pragma unroll
    for (int k=0;k<8;k++) g_fsel[b*8+k] = z[k]*inv;
}

// ---------------- final select logits: [B,8] = g_si @ selF_W + selF_b ----------------
__global__ void __launch_bounds__(256) gemm_selF(const float* __restrict__ W, const float* __restrict__ bias)
{
    __shared__ float Ws[2048];
    int tid = threadIdx.x;
    for (int idx = tid; idx < 2048; idx += 256) Ws[idx] = W[idx];
    __syncthreads();
    int b = blockIdx.x*32 + (tid >> 3);
    int n = tid & 7;
    const float* ap = g_si + (size_t)b*256;
    float acc = bias[n];
    #pragma unroll 8
    for (int k=0;k<256;k++) acc += ap[k]*Ws[k*8+n];
    g_fraw[b*8+n] = acc;
}

// ---------------- fused bn2 + select cascade + final select + last GEMM ----------------
__global__ void __launch_bounds__(256) cascade(
    const float* __restrict__ g2, const float* __restrict__ b2,
    const float* __restrict__ lastW, const float* __restrict__ lastb,
    float* __restrict__ out)
{
    int b = blockIdx.x;
    int tid = threadIdx.x;        // h = 0..255
    __shared__ float Ssh[64];
    __shared__ float fs[8];
    __shared__ float ov[256];

    float p[8];
    #pragma unroll
    for (int m=0;m<8;m++) {
        int c = m*256 + tid;
        float v = g_hbig[((size_t)m*BATCH + b)*256 + tid];
        p[m] = (v - g_mean2[c]) * g_istd2[c] * g2[c] + b2[c];
    }

    for (int l=0;l<3;l++) {
        if (tid < 64) Ssh[tid] = g_gsel[(size_t)(2-l)*BATCH*64 + (size_t)b*64 + tid];
        __syncthreads();
        float np[8];
        #pragma unroll
        for (int m=0;m<8;m++) {
            float a = 0.f;
            #pragma unroll
            for (int k=0;k<8;k++) a += Ssh[m*8+k]*p[k];
            np[m] = fmaxf(a, 0.f);
        }
        #pragma unroll
        for (int m=0;m<8;m++) p[m] = np[m];
        __syncthreads();
    }

    if (tid < 8) fs[tid] = g_fsel[b*8+tid];
    __syncthreads();
    float o = 0.f;
    #pragma unroll
    for (int m=0;m<8;m++) o += fs[m]*p[m];
    ov[tid] = o;
    __syncthreads();

    if (tid < 18) {
        float acc = lastb[tid];
        for (int k=0;k<256;k++) acc += ov[k]*lastW[k*18+tid];
        out[(size_t)b*18 + tid] = acc;
    }
}

// ---------------- launch ----------------
extern "C" void kernel_launch(void* const* d_in, const int* in_sizes, int n_in,
                              void* d_out, int out_size)
{
    const float* x       = (const float*)d_in[0];
    const float* embIn   = (const float*)d_in[1];
    const float* u_sel   = (const float*)d_in[2];
    const float* u_fin   = (const float*)d_in[3];
    const float* base_W0 = (const float*)d_in[4];
    const float* base_b0 = (const float*)d_in[5];
    const float* base_W1 = (const float*)d_in[6];
    const float* base_b1 = (const float*)d_in[7];
    const float* em_W0   = (const float*)d_in[8];
    const float* em_b0   = (const float*)d_in[9];
    const float* gat_W0  = (const float*)d_in[10];
    const float* gat_b0  = (const float*)d_in[11];
    const float* gat_W1  = (const float*)d_in[12];
    const float* gat_b1  = (const float*)d_in[13];
    const float* sel_W   = (const float*)d_in[14];
    const float* sel_b   = (const float*)d_in[15];
    const float* selF_W  = (const float*)d_in[16];
    const float* selF_b  = (const float*)d_in[17];
    const float* cond_W  = (const float*)d_in[18];
    const float* cond_b  = (const float*)d_in[19];
    const float* mod_W   = (const float*)d_in[20];
    const float* mod_b   = (const float*)d_in[21];
    const float* last_W  = (const float*)d_in[22];
    const float* last_b  = (const float*)d_in[23];
    // bn1_g/bn1_b at 24/25, bn2_g/bn2_b at 26/27
    const float* bn1_g   = (const float*)d_in[24];
    const float* bn1_b   = (const float*)d_in[25];
    const float* bn2_g   = (const float*)d_in[26];
    const float* bn2_b   = (const float*)d_in[27];
    float* out = (float*)d_out;

    float *p_h400, *p_out, *p_tmp, *p_emb, *p_si, *p_logit, *p_hbig;
    float *p_psum1, *p_psq1, *p_psum2, *p_psq2, *p_mean1, *p_istd1, *p_mean2, *p_istd2;
    cudaGetSymbolAddress((void**)&p_h400,  g_h400);
    cudaGetSymbolAddress((void**)&p_out,   g_out);
    cudaGetSymbolAddress((void**)&p_tmp,   g_tmp);
    cudaGetSymbolAddress((void**)&p_emb,   g_emb);
    cudaGetSymbolAddress((void**)&p_si,    g_si);
    cudaGetSymbolAddress((void**)&p_logit, g_logit);
    cudaGetSymbolAddress((void**)&p_hbig,  g_hbig);
    cudaGetSymbolAddress((void**)&p_psum1, g_psum1);
    cudaGetSymbolAddress((void**)&p_psq1,  g_psq1);
    cudaGetSymbolAddress((void**)&p_psum2, g_psum2);
    cudaGetSymbolAddress((void**)&p_psq2,  g_psq2);
    cudaGetSymbolAddress((void**)&p_mean1, g_mean1);
    cudaGetSymbolAddress((void**)&p_istd1, g_istd1);
    cudaGetSymbolAddress((void**)&p_mean2, g_mean2);
    cudaGetSymbolAddress((void**)&p_istd2, g_istd2);

    dim3 blk(256);
    auto grid2 = [](int N){ return dim3((unsigned)((N+127)/128), BATCH/128); };

    // base path: out = relu(x@W0+b0)@W1 + b1
    sgemm<<<grid2(400), blk>>>(x,      base_W0, base_b0, p_h400, nullptr, nullptr, 400, 128, EPI_RELU);
    sgemm<<<grid2(256), blk>>>(p_h400, base_W1, base_b1, p_out,  nullptr, nullptr, 256, 400, EPI_NONE);

    // embedding path
    sgemm<<<grid2(400), blk>>>(embIn,  em_W0,  em_b0,  p_h400, nullptr, nullptr, 400, 128, EPI_RELU);
    sgemm<<<grid2(256), blk>>>(p_h400, gat_W0, gat_b0, p_tmp,  nullptr, nullptr, 256, 400, EPI_RELU);
    sgemm<<<grid2(256), blk>>>(p_tmp,  gat_W1, gat_b1, p_emb,  p_si,    nullptr, 256, 256, EPI_DUAL);

    // select loop
    for (int i = 0; i < 3; i++) {
        sgemm<<<grid2(64),  blk>>>(p_si, sel_W + (size_t)i*256*64, sel_b + i*64,
                                   p_logit, nullptr, nullptr, 64, 256, EPI_TANH);
        gumbel_sel<<<(BATCH*8+255)/256, blk>>>(u_sel, i);
        sgemm<<<grid2(256), blk>>>(p_logit, cond_W + (size_t)i*64*256, cond_b + i*256,
                                   p_si, nullptr, p_emb, 256, 64, EPI_MULRELU);
    }

    // final select
    gemm_selF<<<BATCH/32, blk>>>(selF_W, selF_b);
    gumbel_fin<<<(BATCH+255)/256, blk>>>(u_fin);

    // bn1 stats over g_out
    colstats<<<dim3(1, NPART), blk>>>(p_out, p_psum1, p_psq1, 256);
    bnfinal<<<1, blk>>>(p_psum1, p_psq1, p_mean1, p_istd1, 256);

    // mod einsum (bn1 fused into A load)
    modgemm<<<dim3(2, BATCH/128, 8), blk>>>(mod_W, mod_b, bn1_g, bn1_b);

    // bn2 stats over g_hbig (8 slabs)
    colstats<<<dim3(8, NPART), blk>>>(p_hbig, p_psum2, p_psq2, 2048);
    bnfinal<<<8, blk>>>(p_psum2, p_psq2, p_mean2, p_istd2, 2048);

    // fused bn2 + cascade + final select + last layer
    cascade<<<BATCH, blk>>>(bn2_g, bn2_b, last_W, last_b, out);
}

// round 5
// speedup vs baseline: 1.1152x; 1.1152x over previous
#include <cuda_runtime.h>
#include <cuda_bf16.h>
#include <math.h>
#include <stdint.h>
#include <mma.h>

using namespace nvcuda;

#define BATCH 16384

// ---------------- scratch (static device arrays; no allocations) ----------------
__device__ float g_h400 [BATCH*400];
__device__ float g_out  [BATCH*256];
__device__ float g_tmp  [BATCH*256];
__device__ float g_emb  [BATCH*256];
__device__ float g_si   [BATCH*256];
__device__ float g_logit[BATCH*64];
__device__ float g_gsel [3*BATCH*64];
__device__ float g_fraw [BATCH*8];
__device__ float g_fsel [BATCH*8];
__device__ float g_hbig [(size_t)8*BATCH*256];

// deterministic two-stage batchnorm reductions (no atomics)
#define NPART 64
__device__ float g_psum1[NPART*256],  g_psq1[NPART*256];
__device__ float g_psum2[NPART*2048], g_psq2[NPART*2048];
__device__ float g_mean1[256],  g_istd1[256];
__device__ float g_mean2[2048], g_istd2[2048];

enum { EPI_NONE=0, EPI_RELU=1, EPI_TANH=2, EPI_MULRELU=3, EPI_DUAL=4 };

// ---------------- generic fp32 SGEMM (R1, verified) ----------------
__global__ void __launch_bounds__(256) sgemm(
    const float* __restrict__ A, const float* __restrict__ Bw,
    const float* __restrict__ bias, float* __restrict__ C,
    float* __restrict__ C2, const float* __restrict__ aux,
    int N, int K, int epi)
{
    __shared__ float As[16][128];
    __shared__ float Bs[16][128];
    int tid = threadIdx.x;
    int tx = tid & 15, ty = tid >> 4;
    int rowBase = blockIdx.y * 128;
    int colBase = blockIdx.x * 128;

    float acc[8][8];
    #pragma unroll
    for (int i=0;i<8;i++)
        #pragma unroll
        for (int j=0;j<8;j++) acc[i][j]=0.f;

    int aRow = tid >> 1;
    int aCol = (tid & 1) * 8;
    int bRow = tid >> 4;
    int bCol = (tid & 15) * 8;

    for (int kt = 0; kt < K; kt += 16) {
        {
            const float* ap = A + (size_t)(rowBase + aRow) * K + kt + aCol;
            float4 v0 = *(const float4*)(ap);
            float4 v1 = *(const float4*)(ap + 4);
            As[aCol+0][aRow]=v0.x; As[aCol+1][aRow]=v0.y; As[aCol+2][aRow]=v0.z; As[aCol+3][aRow]=v0.w;
            As[aCol+4][aRow]=v1.x; As[aCol+5][aRow]=v1.y; As[aCol+6][aRow]=v1.z; As[aCol+7][aRow]=v1.w;
        }
        {
            int gc = colBase + bCol;
            const float* bp = Bw + (size_t)(kt + bRow) * N + gc;
            if (gc + 7 < N) {
                *(float4*)&Bs[bRow][bCol]   = *(const float4*)(bp);
                *(float4*)&Bs[bRow][bCol+4] = *(const float4*)(bp + 4);
            } else {
                #pragma unroll
                for (int e=0;e<8;e++)
                    Bs[bRow][bCol+e] = (gc+e < N) ? bp[e] : 0.f;
            }
        }
        __syncthreads();
        #pragma unroll
        for (int k=0;k<16;k++) {
            float4 a0 = *(const float4*)&As[k][ty*8];
            float4 a1 = *(const float4*)&As[k][ty*8+4];
            float4 b0 = *(const float4*)&Bs[k][tx*8];
            float4 b1 = *(const float4*)&Bs[k][tx*8+4];
            float av[8]={a0.x,a0.y,a0.z,a0.w,a1.x,a1.y,a1.z,a1.w};
            float bv[8]={b0.x,b0.y,b0.z,b0.w,b1.x,b1.y,b1.z,b1.w};
            #pragma unroll
            for (int i=0;i<8;i++)
                #pragma unroll
                for (int j=0;j<8;j++)
                    acc[i][j] += av[i]*bv[j];
        }
        __syncthreads();
    }

    #pragma unroll
    for (int i=0;i<8;i++) {
        int row = rowBase + ty*8 + i;
        #pragma unroll
        for (int j=0;j<8;j++) {
            int col = colBase + tx*8 + j;
            if (col < N) {
                float v = acc[i][j] + bias[col];
                size_t idx = (size_t)row * N + col;
                if      (epi == EPI_NONE)    C[idx] = v;
                else if (epi == EPI_RELU)    C[idx] = fmaxf(v, 0.f);
                else if (epi == EPI_TANH)    C[idx] = tanhf(v);
                else if (epi == EPI_MULRELU) C[idx] = fmaxf(v * aux[idx], 0.f);
                else                         { C[idx] = v; C2[idx] = fmaxf(v, 0.f); }
            }
        }
    }
}

// =======================================================================
//  EXPERIMENT: mod einsum on tensor cores. Minimal straight-line
//  split-bf16 wmma (m16n16k16). hbig[m] = bn1affine(out) @ mod_W[m].
//  (mod_b omitted: exactly cancelled by the following batchnorm.)
//  128x128 tile, 256 threads, 8 warps x (64x32), single smem buffer.
// =======================================================================
#define ASTRB 40    // A smem row stride (bf16): hi at k 0..15, lo at 16..31
#define BSTRB 264   // B smem row stride (bf16): hi at n 0..127, lo at 128..255

__global__ void __launch_bounds__(256) modgemm_tc(
    const float* __restrict__ modW,
    const float* __restrict__ g1, const float* __restrict__ b1)
{
    __shared__ __align__(32) __nv_bfloat16 As[128*ASTRB];
    __shared__ __align__(32) __nv_bfloat16 Bs[16*BSTRB];

    const int tid  = threadIdx.x;
    const int wid  = tid >> 5;
    const int warpM = (wid >> 2) * 64, warpN = (wid & 3) * 32;
    const int rowBase = blockIdx.y * 128, colBase = blockIdx.x * 128;
    const int m = blockIdx.z;
    const float* Bw = modW + (size_t)m * 65536;

    const int aRow = tid >> 1,  aK = (tid & 1) * 8;   // A: 128 rows x 16 k
    const int bK   = tid >> 4,  bN = (tid & 15) * 8;  // B: 16 k x 128 n

    wmma::fragment<wmma::accumulator,16,16,16,float> acc[4][2];
    #pragma unroll
    for (int mt=0;mt<4;mt++)
        #pragma unroll
        for (int nt=0;nt<2;nt++)
            wmma::fill_fragment(acc[mt][nt], 0.f);

    for (int kt = 0; kt < 256; kt += 16) {
        // --- A tile: bn1-transformed g_out, split hi/lo ---
        {
            const float* ap = g_out + (size_t)(rowBase + aRow) * 256 + kt + aK;
            #pragma unroll
            for (int e=0;e<8;e++) {
                int k = kt + aK + e;
                float v = (ap[e] - g_mean1[k]) * g_istd1[k] * g1[m*256+k] + b1[m*256+k];
                __nv_bfloat16 h = __float2bfloat16(v);
                __nv_bfloat16 l = __float2bfloat16(v - __bfloat162float(h));
                As[aRow*ASTRB + aK + e]      = h;
                As[aRow*ASTRB + aK + e + 16] = l;
            }
        }
        // --- B tile: mod_W[m], split hi/lo ---
        {
            const float* bp = Bw + (size_t)(kt + bK) * 256 + colBase + bN;
            #pragma unroll
            for (int e=0;e<8;e++) {
                float v = bp[e];
                __nv_bfloat16 h = __float2bfloat16(v);
                __nv_bfloat16 l = __float2bfloat16(v - __bfloat162float(h));
                Bs[bK*BSTRB + bN + e]       = h;
                Bs[bK*BSTRB + bN + e + 128] = l;
            }
        }
        __syncthreads();

        wmma::fragment<wmma::matrix_a,16,16,16,__nv_bfloat16,wmma::row_major> ah[4], al[4];
        wmma::fragment<wmma::matrix_b,16,16,16,__nv_bfloat16,wmma::row_major> bh[2], bl[2];
        #pragma unroll
        for (int mt=0;mt<4;mt++) {
            wmma::load_matrix_sync(ah[mt], &As[(warpM + mt*16)*ASTRB],      ASTRB);
            wmma::load_matrix_sync(al[mt], &As[(warpM + mt*16)*ASTRB + 16], ASTRB);
        }
        #pragma unroll
        for (int nt=0;nt<2;nt++) {
            wmma::load_matrix_sync(bh[nt], &Bs[warpN + nt*16],       BSTRB);
            wmma::load_matrix_sync(bl[nt], &Bs[warpN + nt*16 + 128], BSTRB);
        }
        #pragma unroll
        for (int mt=0;mt<4;mt++)
            #pragma unroll
            for (int nt=0;nt<2;nt++) {
                wmma::mma_sync(acc[mt][nt], ah[mt], bh[nt], acc[mt][nt]);
                wmma::mma_sync(acc[mt][nt], ah[mt], bl[nt], acc[mt][nt]);
                wmma::mma_sync(acc[mt][nt], al[mt], bh[nt], acc[mt][nt]);
            }
        __syncthreads();
    }

    // epilogue: no bias (cancelled by bn2) -> store fragments straight to global
    #pragma unroll
    for (int mt=0; mt<4; mt++) {
        float* dst = &g_hbig[((size_t)m*BATCH + rowBase + warpM + mt*16)*256 + colBase + warpN];
        wmma::store_matrix_sync(dst,      acc[mt][0], 256, wmma::mem_row_major);
        wmma::store_matrix_sync(dst + 16, acc[mt][1], 256, wmma::mem_row_major);
    }
}

// ---------------- batchnorm stats (deterministic 2-stage) ----------------
__global__ void colstats(const float* __restrict__ X,
                         float* __restrict__ psum, float* __restrict__ psq,
                         int ncols)
{
    int slab = blockIdx.x;
    int col  = threadIdx.x;
    int c    = slab*256 + col;
    const float* base = X + (size_t)slab * BATCH * 256;
    int rpb = BATCH / NPART;
    int r0  = blockIdx.y * rpb;
    float s = 0.f, q = 0.f;
    for (int r = r0; r < r0 + rpb; r++) {
        float v = base[(size_t)r*256 + col];
        s += v; q += v*v;
    }
    psum[(size_t)blockIdx.y*ncols + c] = s;
    psq [(size_t)blockIdx.y*ncols + c] = q;
}

__global__ void bnfinal(const float* __restrict__ psum, const float* __restrict__ psq,
                        float* __restrict__ mean, float* __restrict__ istd, int n)
{
    int i = blockIdx.x*blockDim.x + threadIdx.x;
    if (i >= n) return;
    float s = 0.f, q = 0.f;
    for (int p = 0; p < NPART; p++) { s += psum[(size_t)p*n + i]; q += psq[(size_t)p*n + i]; }
    float mu  = s * (1.f/BATCH);
    float var = q * (1.f/BATCH) - mu*mu;
    mean[i] = mu;
    istd[i] = rsqrtf(var + 1e-5f);
}

// ---------------- gumbel softmax ----------------
__device__ __forceinline__ float gnoise(float u) {
    u = fminf(fmaxf(u, 1e-10f), 1.0f - 1e-7f);
    return -logf(-logf(u));
}

__global__ void gumbel_sel(const float* __restrict__ u, int i)
{
    int t = blockIdx.x*blockDim.x + threadIdx.x;
    if (t >= BATCH*8) return;
    int b = t >> 3, m = t & 7;
    const float* lp = g_logit + b*64 + m*8;
    const float* up = u + (size_t)b*192 + i*64 + m*8;
    float z[8]; float mx = -3.4e38f;
    #pragma unroll
    for (int k=0;k<8;k++){ z[k] = lp[k] + gnoise(up[k]); mx = fmaxf(mx, z[k]); }
    float s = 0.f;
    #pragma unroll
    for (int k=0;k<8;k++){ z[k] = expf(z[k]-mx); s += z[k]; }
    float inv = 1.f/s;
    float* op = g_gsel + (size_t)i*BATCH*64 + b*64 + m*8;
    #pragma unroll
    for (int k=0;k<8;k++) op[k] = z[k]*inv;
}

__global__ void gumbel_fin(const float* __restrict__ u)
{
    int b = blockIdx.x*blockDim.x + threadIdx.x;
    if (b >= BATCH) return;
    float z[8]; float mx = -3.4e38f;
    #pragma unroll
    for (int k=0;k<8;k++){ z[k] = g_fraw[b*8+k] + gnoise(u[b*8+k]); mx = fmaxf(mx, z[k]); }
    float s = 0.f;
    #pragma unroll
    for (int k=0;k<8;k++){ z[k] = expf(z[k]-mx); s += z[k]; }
    float inv = 1.f/s;
    #pragma unroll
    for (int k=0;k<8;k++) g_fsel[b*8+k] = z[k]*inv;
}

// ---------------- final select logits ----------------
__global__ void __launch_bounds__(256) gemm_selF(const float* __restrict__ W, const float* __restrict__ bias)
{
    __shared__ float Ws[2048];
    int tid = threadIdx.x;
    for (int idx = tid; idx < 2048; idx += 256) Ws[idx] = W[idx];
    __syncthreads();
    int b = blockIdx.x*32 + (tid >> 3);
    int n = tid & 7;
    const float* ap = g_si + (size_t)b*256;
    float acc = bias[n];
    #pragma unroll 8
    for (int k=0;k<256;k++) acc += ap[k]*Ws[k*8+n];
    g_fraw[b*8+n] = acc;
}

// ---------------- fused bn2 + select cascade + final select + last GEMM ----------------
__global__ void __launch_bounds__(256) cascade(
    const float* __restrict__ g2, const float* __restrict__ b2,
    const float* __restrict__ lastW, const float* __restrict__ lastb,
    float* __restrict__ out)
{
    int b = blockIdx.x;
    int tid = threadIdx.x;
    __shared__ float Ssh[64];
    __shared__ float fs[8];
    __shared__ float ov[256];

    float p[8];
    #pragma unroll
    for (int m=0;m<8;m++) {
        int c = m*256 + tid;
        float v = g_hbig[((size_t)m*BATCH + b)*256 + tid];
        p[m] = (v - g_mean2[c]) * g_istd2[c] * g2[c] + b2[c];
    }

    for (int l=0;l<3;l++) {
        if (tid < 64) Ssh[tid] = g_gsel[(size_t)(2-l)*BATCH*64 + (size_t)b*64 + tid];
        __syncthreads();
        float np[8];
        #pragma unroll
        for (int m=0;m<8;m++) {
            float a = 0.f;
            #pragma unroll
            for (int k=0;k<8;k++) a += Ssh[m*8+k]*p[k];
            np[m] = fmaxf(a, 0.f);
        }
        #pragma unroll
        for (int m=0;m<8;m++) p[m] = np[m];
        __syncthreads();
    }

    if (tid < 8) fs[tid] = g_fsel[b*8+tid];
    __syncthreads();
    float o = 0.f;
    #pragma unroll
    for (int m=0;m<8;m++) o += fs[m]*p[m];
    ov[tid] = o;
    __syncthreads();

    if (tid < 18) {
        float acc = lastb[tid];
        for (int k=0;k<256;k++) acc += ov[k]*lastW[k*18+tid];
        out[(size_t)b*18 + tid] = acc;
    }
}

// ---------------- launch ----------------
extern "C" void kernel_launch(void* const* d_in, const int* in_sizes, int n_in,
                              void* d_out, int out_size)
{
    const float* x       = (const float*)d_in[0];
    const float* embIn   = (const float*)d_in[1];
    const float* u_sel   = (const float*)d_in[2];
    const float* u_fin   = (const float*)d_in[3];
    const float* base_W0 = (const float*)d_in[4];
    const float* base_b0 = (const float*)d_in[5];
    const float* base_W1 = (const float*)d_in[6];
    const float* base_b1 = (const float*)d_in[7];
    const float* em_W0   = (const float*)d_in[8];
    const float* em_b0   = (const float*)d_in[9];
    const float* gat_W0  = (const float*)d_in[10];
    const float* gat_b0  = (const float*)d_in[11];
    const float* gat_W1  = (const float*)d_in[12];
    const float* gat_b1  = (const float*)d_in[13];
    const float* sel_W   = (const float*)d_in[14];
    const float* sel_b   = (const float*)d_in[15];
    const float* selF_W  = (const float*)d_in[16];
    const float* selF_b  = (const float*)d_in[17];
    const float* cond_W  = (const float*)d_in[18];
    const float* cond_b  = (const float*)d_in[19];
    const float* mod_W   = (const float*)d_in[20];
    const float* mod_b   = (const float*)d_in[21];
    const float* last_W  = (const float*)d_in[22];
    const float* last_b  = (const float*)d_in[23];
    const float* bn1_g   = (const float*)d_in[24];
    const float* bn1_b   = (const float*)d_in[25];
    const float* bn2_g   = (const float*)d_in[26];
    const float* bn2_b   = (const float*)d_in[27];
    float* out = (float*)d_out;

    float *p_h400, *p_out, *p_tmp, *p_emb, *p_si, *p_logit, *p_hbig;
    float *p_psum1, *p_psq1, *p_psum2, *p_psq2, *p_mean1, *p_istd1, *p_mean2, *p_istd2;
    cudaGetSymbolAddress((void**)&p_h400,  g_h400);
    cudaGetSymbolAddress((void**)&p_out,   g_out);
    cudaGetSymbolAddress((void**)&p_tmp,   g_tmp);
    cudaGetSymbolAddress((void**)&p_emb,   g_emb);
    cudaGetSymbolAddress((void**)&p_si,    g_si);
    cudaGetSymbolAddress((void**)&p_logit, g_logit);
    cudaGetSymbolAddress((void**)&p_hbig,  g_hbig);
    cudaGetSymbolAddress((void**)&p_psum1, g_psum1);
    cudaGetSymbolAddress((void**)&p_psq1,  g_psq1);
    cudaGetSymbolAddress((void**)&p_psum2, g_psum2);
    cudaGetSymbolAddress((void**)&p_psq2,  g_psq2);
    cudaGetSymbolAddress((void**)&p_mean1, g_mean1);
    cudaGetSymbolAddress((void**)&p_istd1, g_istd1);
    cudaGetSymbolAddress((void**)&p_mean2, g_mean2);
    cudaGetSymbolAddress((void**)&p_istd2, g_istd2);

    dim3 blk(256);
    auto grid2 = [](int N){ return dim3((unsigned)((N+127)/128), BATCH/128); };

    // base path: out = relu(x@W0+b0)@W1 + b1
    sgemm<<<grid2(400), blk>>>(x,      base_W0, base_b0, p_h400, nullptr, nullptr, 400, 128, EPI_RELU);
    sgemm<<<grid2(256), blk>>>(p_h400, base_W1, base_b1, p_out,  nullptr, nullptr, 256, 400, EPI_NONE);

    // embedding path
    sgemm<<<grid2(400), blk>>>(embIn,  em_W0,  em_b0,  p_h400, nullptr, nullptr, 400, 128, EPI_RELU);
    sgemm<<<grid2(256), blk>>>(p_h400, gat_W0, gat_b0, p_tmp,  nullptr, nullptr, 256, 400, EPI_RELU);
    sgemm<<<grid2(256), blk>>>(p_tmp,  gat_W1, gat_b1, p_emb,  p_si,    nullptr, 256, 256, EPI_DUAL);

    // select loop
    for (int i = 0; i < 3; i++) {
        sgemm<<<grid2(64),  blk>>>(p_si, sel_W + (size_t)i*256*64, sel_b + i*64,
                                   p_logit, nullptr, nullptr, 64, 256, EPI_TANH);
        gumbel_sel<<<(BATCH*8+255)/256, blk>>>(u_sel, i);
        sgemm<<<grid2(256), blk>>>(p_logit, cond_W + (size_t)i*64*256, cond_b + i*256,
                                   p_si, nullptr, p_emb, 256, 64, EPI_MULRELU);
    }

    // final select
    gemm_selF<<<BATCH/32, blk>>>(selF_W, selF_b);
    gumbel_fin<<<(BATCH+255)/256, blk>>>(u_fin);

    // bn1 stats over g_out
    colstats<<<dim3(1, NPART), blk>>>(p_out, p_psum1, p_psq1, 256);
    bnfinal<<<1, blk>>>(p_psum1, p_psq1, p_mean1, p_istd1, 256);

    // mod einsum — TENSOR-CORE EXPERIMENT (bn1 fused into A, mod_b exactly
    // cancelled by bn2 so no bias needed)
    {
        dim3 grid(2, BATCH/128, 8);
        modgemm_tc<<<grid, blk>>>(mod_W, bn1_g, bn1_b);
    }

    // bn2 stats over g_hbig
    colstats<<<dim3(8, NPART), blk>>>(p_hbig, p_psum2, p_psq2, 2048);
    bnfinal<<<8, blk>>>(p_psum2, p_psq2, p_mean2, p_istd2, 2048);

    // fused bn2 + cascade + final select + last layer
    cascade<<<BATCH, blk>>>(bn2_g, bn2_b, last_W, last_b, out);
}